// round 11
// baseline (speedup 1.0000x reference)
#include <cuda_runtime.h>
#include <cuda_fp16.h>

#define D 128
#define MAX_N 100000
#define MBLK 64            // rows of x per GEMM block
#define PADH 136           // smem row stride in halves

// support = x@W + b, stored fp16 (25.6 MB)
__device__ __half g_support_h[(size_t)MAX_N * D];
// W transposed + converted to fp16: Wt[n][k]
__device__ __half g_Wt_h[D * D];
// CSR row pointers for destination nodes
__device__ int g_rowptr[MAX_N + 1];

// ---------------------------------------------------------------------------
// packed f32x2 helpers (sm_103a: fma.rn.f32x2 is PTX-only)
// ---------------------------------------------------------------------------
__device__ __forceinline__ unsigned long long pk2(float lo, float hi) {
    unsigned long long r;
    asm("mov.b64 %0, {%1, %2};" : "=l"(r) : "f"(lo), "f"(hi));
    return r;
}
__device__ __forceinline__ float2 upk2(unsigned long long v) {
    float2 r;
    asm("mov.b64 {%0, %1}, %2;" : "=f"(r.x), "=f"(r.y) : "l"(v));
    return r;
}
__device__ __forceinline__ unsigned long long ffma2p(unsigned long long a,
                                                     unsigned long long b,
                                                     unsigned long long c) {
    unsigned long long d;
    asm("fma.rn.f32x2 %0, %1, %2, %3;" : "=l"(d) : "l"(a), "l"(b), "l"(c));
    return d;
}

// ---------------------------------------------------------------------------
// prep: Wt_h[n][k] = fp16(W[k][n])
// ---------------------------------------------------------------------------
__global__ void prep_kernel(const float* __restrict__ W, __half* __restrict__ Wt) {
    int i = blockIdx.x * blockDim.x + threadIdx.x;
    if (i < D * D) {
        int k = i >> 7, n = i & 127;
        Wt[n * D + k] = __float2half(W[i]);
    }
}

// ---------------------------------------------------------------------------
// rowptr: edst sorted -> rp[d] = first edge with dst >= d. O(E+N).
// ---------------------------------------------------------------------------
__global__ void rowptr_kernel(const int* __restrict__ edst,
                              int* __restrict__ rp, int E, int N) {
    int e = blockIdx.x * blockDim.x + threadIdx.x;
    if (e >= E) return;
    int d  = edst[e];
    int dp = (e == 0) ? -1 : edst[e - 1];
    for (int k = dp + 1; k <= d; k++) rp[k] = e;
    if (e == E - 1)
        for (int k = d + 1; k <= N; k++) rp[k] = E;
}

__device__ __forceinline__ void mma_f16(float d[4], unsigned a0, unsigned a1,
                                        unsigned a2, unsigned a3,
                                        unsigned b0, unsigned b1) {
    asm volatile(
        "mma.sync.aligned.m16n8k16.row.col.f32.f16.f16.f32 "
        "{%0,%1,%2,%3}, {%4,%5,%6,%7}, {%8,%9}, {%0,%1,%2,%3};"
        : "+f"(d[0]), "+f"(d[1]), "+f"(d[2]), "+f"(d[3])
        : "r"(a0), "r"(a1), "r"(a2), "r"(a3), "r"(b0), "r"(b1));
}

// ---------------------------------------------------------------------------
// GEMM: support = fp16(x@W + b) via fp16 mma m16n8k16. (Memory-floor bound.)
// ---------------------------------------------------------------------------
__global__ void __launch_bounds__(256) gemm_mma_kernel(
        const float* __restrict__ x,
        const __half* __restrict__ Wt,
        const float* __restrict__ b,
        __half* __restrict__ sup, int N) {
    extern __shared__ __half smem[];
    __half* sX = smem;                 // 64  x PADH halves
    __half* sW = smem + MBLK * PADH;   // 128 x PADH halves ([n][k])

    const int tid  = threadIdx.x;
    const int lane = tid & 31;
    const int w    = tid >> 5;
    const int wm   = w & 3;
    const int wn   = w >> 2;
    const int g    = lane >> 2;
    const int tig  = lane & 3;

    const int row0 = blockIdx.x * MBLK;

    const uint4* Wv = (const uint4*)Wt;
    #pragma unroll
    for (int i = tid; i < 128 * 16; i += 256) {
        int r = i >> 4, c = i & 15;
        *(uint4*)(sW + r * PADH + c * 8) = Wv[i];
    }
    const float4* xv = (const float4*)x;
    #pragma unroll
    for (int i = tid; i < MBLK * 32; i += 256) {
        int r = i >> 5, c = i & 31;
        float4 v = make_float4(0.f, 0.f, 0.f, 0.f);
        if (row0 + r < N) v = xv[(size_t)(row0 + r) * 32 + c];
        __half2 h0 = __floats2half2_rn(v.x, v.y);
        __half2 h1 = __floats2half2_rn(v.z, v.w);
        uint2 p = make_uint2(*(unsigned*)&h0, *(unsigned*)&h1);
        *(uint2*)(sX + r * PADH + c * 4) = p;
    }
    __syncthreads();

    float acc[8][4];
    #pragma unroll
    for (int t = 0; t < 8; t++)
        #pragma unroll
        for (int j = 0; j < 4; j++) acc[t][j] = 0.f;

    const int ar0 = wm * 16 + g;
    const int ar1 = ar0 + 8;

    #pragma unroll
    for (int k0 = 0; k0 < D; k0 += 16) {
        unsigned a0 = *(const unsigned*)(sX + ar0 * PADH + k0 + 2 * tig);
        unsigned a1 = *(const unsigned*)(sX + ar1 * PADH + k0 + 2 * tig);
        unsigned a2 = *(const unsigned*)(sX + ar0 * PADH + k0 + 2 * tig + 8);
        unsigned a3 = *(const unsigned*)(sX + ar1 * PADH + k0 + 2 * tig + 8);
        #pragma unroll
        for (int t = 0; t < 8; t++) {
            int n0 = wn * 64 + t * 8;
            unsigned b0 = *(const unsigned*)(sW + (n0 + g) * PADH + k0 + 2 * tig);
            unsigned b1 = *(const unsigned*)(sW + (n0 + g) * PADH + k0 + 2 * tig + 8);
            mma_f16(acc[t], a0, a1, a2, a3, b0, b1);
        }
    }

    const int gr0 = row0 + wm * 16 + g;
    const int gr1 = gr0 + 8;
    #pragma unroll
    for (int t = 0; t < 8; t++) {
        int col = wn * 64 + t * 8 + 2 * tig;
        float bx = b[col], by = b[col + 1];
        if (gr0 < N) {
            __half2 h = __floats2half2_rn(acc[t][0] + bx, acc[t][1] + by);
            *(__half2*)(sup + (size_t)gr0 * D + col) = h;
        }
        if (gr1 < N) {
            __half2 h = __floats2half2_rn(acc[t][2] + bx, acc[t][3] + by);
            *(__half2*)(sup + (size_t)gr1 * D + col) = h;
        }
    }
}

// ---------------------------------------------------------------------------
// CSR pull: one warp per destination node; lane owns 4 features (uint2
// gather). Metadata via warp-uniform LDG (L1 broadcast). Packed f32x2 FMA,
// manual unroll-2 with two independent accumulator chains. No atomics;
// one STG.128 per lane per node.
// ---------------------------------------------------------------------------
__global__ void __launch_bounds__(256) scatter_csr_kernel(
        const __half* __restrict__ sup,
        const float* __restrict__ ew,
        const int* __restrict__ esrc,
        const int* __restrict__ rp,
        float* __restrict__ out, int N) {
    const int warp = (blockIdx.x * blockDim.x + threadIdx.x) >> 5;
    const int lane = threadIdx.x & 31;
    if (warp >= N) return;

    const int beg = rp[warp];
    const int end = rp[warp + 1];

    const uint2* supv = (const uint2*)sup;

    // two independent packed-f32x2 accumulator chains
    unsigned long long a01 = pk2(0.f, 0.f), a23 = pk2(0.f, 0.f);
    unsigned long long b01 = pk2(0.f, 0.f), b23 = pk2(0.f, 0.f);

    int e = beg;
    #pragma unroll 2
    for (; e + 2 <= end; e += 2) {
        const int   s0 = __ldg(esrc + e);
        const int   s1 = __ldg(esrc + e + 1);
        const float w0 = __ldg(ew + e);
        const float w1 = __ldg(ew + e + 1);
        uint2 u0 = supv[(size_t)s0 * 32 + lane];
        uint2 u1 = supv[(size_t)s1 * 32 + lane];

        const unsigned long long w0p = pk2(w0, w0);
        float2 f00 = __half22float2(*(__half2*)(&u0.x));
        float2 f01 = __half22float2(*(__half2*)(&u0.y));
        a01 = ffma2p(pk2(f00.x, f00.y), w0p, a01);
        a23 = ffma2p(pk2(f01.x, f01.y), w0p, a23);

        const unsigned long long w1p = pk2(w1, w1);
        float2 f10 = __half22float2(*(__half2*)(&u1.x));
        float2 f11 = __half22float2(*(__half2*)(&u1.y));
        b01 = ffma2p(pk2(f10.x, f10.y), w1p, b01);
        b23 = ffma2p(pk2(f11.x, f11.y), w1p, b23);
    }
    if (e < end) {   // tail edge
        const int   s0 = __ldg(esrc + e);
        const float w0 = __ldg(ew + e);
        uint2 u0 = supv[(size_t)s0 * 32 + lane];
        const unsigned long long w0p = pk2(w0, w0);
        float2 f00 = __half22float2(*(__half2*)(&u0.x));
        float2 f01 = __half22float2(*(__half2*)(&u0.y));
        a01 = ffma2p(pk2(f00.x, f00.y), w0p, a01);
        a23 = ffma2p(pk2(f01.x, f01.y), w0p, a23);
    }

    float2 r01a = upk2(a01), r01b = upk2(b01);
    float2 r23a = upk2(a23), r23b = upk2(b23);
    float4 r = make_float4(r01a.x + r01b.x, r01a.y + r01b.y,
                           r23a.x + r23b.x, r23a.y + r23b.y);
    *(float4*)(out + (size_t)warp * D + lane * 4) = r;
}

extern "C" void kernel_launch(void* const* d_in, const int* in_sizes, int n_in,
                              void* d_out, int out_size) {
    const float* x    = (const float*)d_in[0];
    const float* W    = (const float*)d_in[1];
    const float* b    = (const float*)d_in[2];
    const float* ew   = (const float*)d_in[3];
    const int*   esrc = (const int*)d_in[4];
    const int*   edst = (const int*)d_in[5];
    float* out = (float*)d_out;

    const int N = in_sizes[0] / D;
    const int E = in_sizes[3];

    __half* sup = nullptr;
    cudaGetSymbolAddress((void**)&sup, g_support_h);
    __half* Wt = nullptr;
    cudaGetSymbolAddress((void**)&Wt, g_Wt_h);
    int* rp = nullptr;
    cudaGetSymbolAddress((void**)&rp, g_rowptr);

    prep_kernel<<<(D * D + 255) / 256, 256>>>(W, Wt);
    rowptr_kernel<<<(E + 255) / 256, 256>>>(edst, rp, E, N);

    const int gemm_smem = (MBLK * PADH + D * PADH) * (int)sizeof(__half); // ~52 KB
    cudaFuncSetAttribute(gemm_mma_kernel, cudaFuncAttributeMaxDynamicSharedMemorySize, gemm_smem);

    const int gemm_blocks = (N + MBLK - 1) / MBLK;
    gemm_mma_kernel<<<gemm_blocks, 256, gemm_smem>>>(x, Wt, b, sup, N);

    // one warp per node, 8 warps per block
    const int scat_blocks = (N + 7) / 8;
    scatter_csr_kernel<<<scat_blocks, 256>>>(sup, ew, esrc, rp, out, N);
}

// round 12
// speedup vs baseline: 1.0865x; 1.0865x over previous
#include <cuda_runtime.h>
#include <cuda_fp16.h>

#define D 128
#define MAX_N 100000
#define MBLK 64            // rows of x per GEMM block
#define PADH 136           // smem row stride in halves

// support = x@W + b, stored fp16 (25.6 MB)
__device__ __half g_support_h[(size_t)MAX_N * D];
// W transposed + converted to fp16: Wt[n][k]
__device__ __half g_Wt_h[D * D];
// CSR row pointers for destination nodes
__device__ int g_rowptr[MAX_N + 1];

// ---------------------------------------------------------------------------
// prep: Wt_h[n][k] = fp16(W[k][n])
// ---------------------------------------------------------------------------
__global__ void prep_kernel(const float* __restrict__ W, __half* __restrict__ Wt) {
    int i = blockIdx.x * blockDim.x + threadIdx.x;
    if (i < D * D) {
        int k = i >> 7, n = i & 127;
        Wt[n * D + k] = __float2half(W[i]);
    }
}

// ---------------------------------------------------------------------------
// rowptr: edst sorted -> rp[d] = first edge with dst >= d. O(E+N).
// ---------------------------------------------------------------------------
__global__ void rowptr_kernel(const int* __restrict__ edst,
                              int* __restrict__ rp, int E, int N) {
    int e = blockIdx.x * blockDim.x + threadIdx.x;
    if (e >= E) return;
    int d  = edst[e];
    int dp = (e == 0) ? -1 : edst[e - 1];
    for (int k = dp + 1; k <= d; k++) rp[k] = e;
    if (e == E - 1)
        for (int k = d + 1; k <= N; k++) rp[k] = E;
}

__device__ __forceinline__ void mma_f16(float d[4], unsigned a0, unsigned a1,
                                        unsigned a2, unsigned a3,
                                        unsigned b0, unsigned b1) {
    asm volatile(
        "mma.sync.aligned.m16n8k16.row.col.f32.f16.f16.f32 "
        "{%0,%1,%2,%3}, {%4,%5,%6,%7}, {%8,%9}, {%0,%1,%2,%3};"
        : "+f"(d[0]), "+f"(d[1]), "+f"(d[2]), "+f"(d[3])
        : "r"(a0), "r"(a1), "r"(a2), "r"(a3), "r"(b0), "r"(b1));
}

// ---------------------------------------------------------------------------
// GEMM: support = fp16(x@W + b) via fp16 mma m16n8k16. (Memory-floor bound.)
// ---------------------------------------------------------------------------
__global__ void __launch_bounds__(256) gemm_mma_kernel(
        const float* __restrict__ x,
        const __half* __restrict__ Wt,
        const float* __restrict__ b,
        __half* __restrict__ sup, int N) {
    extern __shared__ __half smem[];
    __half* sX = smem;                 // 64  x PADH halves
    __half* sW = smem + MBLK * PADH;   // 128 x PADH halves ([n][k])

    const int tid  = threadIdx.x;
    const int lane = tid & 31;
    const int w    = tid >> 5;
    const int wm   = w & 3;
    const int wn   = w >> 2;
    const int g    = lane >> 2;
    const int tig  = lane & 3;

    const int row0 = blockIdx.x * MBLK;

    const uint4* Wv = (const uint4*)Wt;
    #pragma unroll
    for (int i = tid; i < 128 * 16; i += 256) {
        int r = i >> 4, c = i & 15;
        *(uint4*)(sW + r * PADH + c * 8) = Wv[i];
    }
    const float4* xv = (const float4*)x;
    #pragma unroll
    for (int i = tid; i < MBLK * 32; i += 256) {
        int r = i >> 5, c = i & 31;
        float4 v = make_float4(0.f, 0.f, 0.f, 0.f);
        if (row0 + r < N) v = xv[(size_t)(row0 + r) * 32 + c];
        __half2 h0 = __floats2half2_rn(v.x, v.y);
        __half2 h1 = __floats2half2_rn(v.z, v.w);
        uint2 p = make_uint2(*(unsigned*)&h0, *(unsigned*)&h1);
        *(uint2*)(sX + r * PADH + c * 4) = p;
    }
    __syncthreads();

    float acc[8][4];
    #pragma unroll
    for (int t = 0; t < 8; t++)
        #pragma unroll
        for (int j = 0; j < 4; j++) acc[t][j] = 0.f;

    const int ar0 = wm * 16 + g;
    const int ar1 = ar0 + 8;

    #pragma unroll
    for (int k0 = 0; k0 < D; k0 += 16) {
        unsigned a0 = *(const unsigned*)(sX + ar0 * PADH + k0 + 2 * tig);
        unsigned a1 = *(const unsigned*)(sX + ar1 * PADH + k0 + 2 * tig);
        unsigned a2 = *(const unsigned*)(sX + ar0 * PADH + k0 + 2 * tig + 8);
        unsigned a3 = *(const unsigned*)(sX + ar1 * PADH + k0 + 2 * tig + 8);
        #pragma unroll
        for (int t = 0; t < 8; t++) {
            int n0 = wn * 64 + t * 8;
            unsigned b0 = *(const unsigned*)(sW + (n0 + g) * PADH + k0 + 2 * tig);
            unsigned b1 = *(const unsigned*)(sW + (n0 + g) * PADH + k0 + 2 * tig + 8);
            mma_f16(acc[t], a0, a1, a2, a3, b0, b1);
        }
    }

    const int gr0 = row0 + wm * 16 + g;
    const int gr1 = gr0 + 8;
    #pragma unroll
    for (int t = 0; t < 8; t++) {
        int col = wn * 64 + t * 8 + 2 * tig;
        float bx = b[col], by = b[col + 1];
        if (gr0 < N) {
            __half2 h = __floats2half2_rn(acc[t][0] + bx, acc[t][1] + by);
            *(__half2*)(sup + (size_t)gr0 * D + col) = h;
        }
        if (gr1 < N) {
            __half2 h = __floats2half2_rn(acc[t][2] + bx, acc[t][3] + by);
            *(__half2*)(sup + (size_t)gr1 * D + col) = h;
        }
    }
}

// ---------------------------------------------------------------------------
// CSR pull, half-warp per node: warp serves 2 nodes; lane owns 8 features of
// its half's node (uint4 = LDG.128 gather, one instruction per 2 edges).
// Metadata: one LDG for src + one for w covers both halves (2 distinct
// addresses per warp -> L1 broadcast). ALL load indices are selected into
// valid ranges (inactive iterations read index 0 with w=0) — no predicated-
// off addresses, no early returns, no pipeline. One store path for all nodes.
// ---------------------------------------------------------------------------
__global__ void __launch_bounds__(256) scatter_csr_kernel(
        const __half* __restrict__ sup,
        const float* __restrict__ ew,
        const int* __restrict__ esrc,
        const int* __restrict__ rp,
        float* __restrict__ out, int N) {
    const int warp = (blockIdx.x * blockDim.x + threadIdx.x) >> 5;
    const int lane = threadIdx.x & 31;
    const int half = lane >> 4;         // which node this half-warp serves
    const int l16  = lane & 15;         // 16 lanes x 8 halves = 128 features
    const int node = warp * 2 + half;
    const bool valid = (node < N);

    int beg = 0, len = 0;
    if (valid) {
        beg = rp[node];
        len = rp[node + 1] - beg;
    }
    const int maxlen = max(len, __shfl_xor_sync(0xffffffffu, len, 16));

    const uint4* supv = (const uint4*)sup;   // 16 uint4 per support row

    float a0 = 0.f, a1 = 0.f, a2 = 0.f, a3 = 0.f;
    float a4 = 0.f, a5 = 0.f, a6 = 0.f, a7 = 0.f;

    for (int j = 0; j < maxlen; j++) {
        const bool act = (j < len);
        const int  idx = act ? (beg + j) : 0;        // always a valid index
        const int  s   = __ldg(esrc + idx);          // in [0, N)
        float      w   = __ldg(ew + idx);
        w = act ? w : 0.f;

        const uint4 u = supv[(size_t)s * 16 + l16];  // always in-bounds

        const float2 f0 = __half22float2(*(const __half2*)(&u.x));
        const float2 f1 = __half22float2(*(const __half2*)(&u.y));
        const float2 f2 = __half22float2(*(const __half2*)(&u.z));
        const float2 f3 = __half22float2(*(const __half2*)(&u.w));
        a0 += w * f0.x; a1 += w * f0.y;
        a2 += w * f1.x; a3 += w * f1.y;
        a4 += w * f2.x; a5 += w * f2.y;
        a6 += w * f3.x; a7 += w * f3.y;
    }

    if (valid) {
        float* o = out + (size_t)node * D + l16 * 8;
        *(float4*)(o)     = make_float4(a0, a1, a2, a3);
        *(float4*)(o + 4) = make_float4(a4, a5, a6, a7);
    }
}

extern "C" void kernel_launch(void* const* d_in, const int* in_sizes, int n_in,
                              void* d_out, int out_size) {
    const float* x    = (const float*)d_in[0];
    const float* W    = (const float*)d_in[1];
    const float* b    = (const float*)d_in[2];
    const float* ew   = (const float*)d_in[3];
    const int*   esrc = (const int*)d_in[4];
    const int*   edst = (const int*)d_in[5];
    float* out = (float*)d_out;

    const int N = in_sizes[0] / D;
    const int E = in_sizes[3];

    __half* sup = nullptr;
    cudaGetSymbolAddress((void**)&sup, g_support_h);
    __half* Wt = nullptr;
    cudaGetSymbolAddress((void**)&Wt, g_Wt_h);
    int* rp = nullptr;
    cudaGetSymbolAddress((void**)&rp, g_rowptr);

    prep_kernel<<<(D * D + 255) / 256, 256>>>(W, Wt);
    rowptr_kernel<<<(E + 255) / 256, 256>>>(edst, rp, E, N);

    const int gemm_smem = (MBLK * PADH + D * PADH) * (int)sizeof(__half); // ~52 KB
    cudaFuncSetAttribute(gemm_mma_kernel, cudaFuncAttributeMaxDynamicSharedMemorySize, gemm_smem);

    const int gemm_blocks = (N + MBLK - 1) / MBLK;
    gemm_mma_kernel<<<gemm_blocks, 256, gemm_smem>>>(x, Wt, b, sup, N);

    // 2 nodes per warp, 8 warps per block -> 16 nodes per block
    const int scat_blocks = (N + 15) / 16;
    scatter_csr_kernel<<<scat_blocks, 256>>>(sup, ew, esrc, rp, out, N);
}